// round 6
// baseline (speedup 1.0000x reference)
#include <cuda_runtime.h>

#define NG      8000
#define NGATE   16000
#define NCTA    125
#define GPC     128      // gates per CTA
#define NGP     64       // gate-pairs per CTA
#define NB      32
#define NP      64
#define NITER   50
#define NT      1024
#define DTF     0.02f
#define INV_DT_SKIP 2.5f

typedef unsigned long long u64;

// ---------------- device scratch ----------------
__device__ float    g_S[4][NB*NP];        // rotating reduction buffers
__device__ float    g_invT[2][NP*NP];     // inverses, j-major scalar: [j*64+i] = inv[i][j]
__device__ unsigned g_counter;

// ---------------- packed f32x2 + memory-order helpers ----------------
__device__ __forceinline__ u64 fma2(u64 a, u64 b, u64 c) {
    u64 d; asm("fma.rn.f32x2 %0, %1, %2, %3;" : "=l"(d) : "l"(a), "l"(b), "l"(c)); return d;
}
__device__ __forceinline__ u64 mul2(u64 a, u64 b) {
    u64 d; asm("mul.rn.f32x2 %0, %1, %2;" : "=l"(d) : "l"(a), "l"(b)); return d;
}
__device__ __forceinline__ u64 add2(u64 a, u64 b) {
    u64 d; asm("add.rn.f32x2 %0, %1, %2;" : "=l"(d) : "l"(a), "l"(b)); return d;
}
__device__ __forceinline__ u64 dup2(float x) {
    unsigned xi = __float_as_uint(x);
    u64 d; asm("mov.b64 %0, {%1, %2};" : "=l"(d) : "r"(xi), "r"(xi)); return d;
}
__device__ __forceinline__ void unpack2(u64 v, float& lo, float& hi) {
    unsigned a, b; asm("mov.b64 {%0, %1}, %2;" : "=r"(a), "=r"(b) : "l"(v));
    lo = __uint_as_float(a); hi = __uint_as_float(b);
}
__device__ __forceinline__ unsigned ldacq(const unsigned* p) {
    unsigned v; asm volatile("ld.acquire.gpu.u32 %0, [%1];" : "=r"(v) : "l"(p)); return v;
}
__device__ __forceinline__ unsigned atom_inc_acqrel(unsigned* p) {
    unsigned v, one = 1u;
    asm volatile("atom.add.acq_rel.gpu.u32 %0, [%1], %2;" : "=r"(v) : "l"(p), "r"(one)); return v;
}
__device__ __forceinline__ void redadd(float* p, float v) {
    asm volatile("red.add.f32 [%0], %1;" :: "l"(p), "f"(v));
}

// ---------------- init: matrix inverses + reset ----------------
__global__ void init_kernel(const float* __restrict__ Ap) {
    __shared__ float M[NP][2*NP + 1];
    __shared__ float fac[NP];
    __shared__ float s_piv;
    int t = threadIdx.x;

    for (int pass = 0; pass < 2; ++pass) {
        float dscale = (pass == 0) ? 1.0f : 3.0f;
        float ascale = (pass == 0) ? DTF : 2.0f * DTF;
        for (int idx = t; idx < NP*NP; idx += 256) {
            int i = idx >> 6, j = idx & 63;
            M[i][j]      = ((i == j) ? dscale : 0.0f) - ascale * Ap[idx];
            M[i][j + NP] = (i == j) ? 1.0f : 0.0f;
        }
        __syncthreads();
        for (int c = 0; c < NP; ++c) {
            if (t == 0) s_piv = 1.0f / M[c][c];
            __syncthreads();
            float ip = s_piv;
            if (t < 2*NP) M[c][t] *= ip;
            if (t < NP)   fac[t] = (t == c) ? 0.0f : M[t][c];
            __syncthreads();
            for (int idx = t; idx < NP * 2 * NP; idx += 256) {
                int r = idx >> 7, j = idx & 127;
                if (r != c) M[r][j] -= fac[r] * M[c][j];
            }
            __syncthreads();
        }
        for (int idx = t; idx < NP*NP; idx += 256) {
            int j = idx >> 6, i = idx & 63;
            g_invT[pass][idx] = M[i][j + NP];   // j-major
        }
        __syncthreads();
    }
    for (int idx = t; idx < 4*NB*NP; idx += 256) ((float*)g_S)[idx] = 0.0f;
    if (t == 0) g_counter = 0u;
    __threadfence();
}

// ---------------- SMEM layout (bytes) ----------------
#define SM_W     0                      // [k 64][gp 64][c 4] u64 (gate-paired)  : 131072
#define SM_P2    131072                 // [gp 64][p 64] u64 (gate-paired)       : 32768
#define SM_F2    163840                 // [gp 64][b 32] u64 (gate-paired)       : 16384
#define SM_AS    180224                 // [k 64][b 32] f32                      : 8192
#define SM_R     188416                 // [j 64][bp 16] u64 (batch-paired)      : 8192
#define SM_INV   196608                 // [j 64][i 64] f32                      : 16384
#define SM_PART  212992                 // [b 32][p 64] u64 partials             : 16384
#define SMEM_TOTAL 229376

extern __shared__ char smem_raw[];

__global__ void __launch_bounds__(NT, 1)
persist_kernel(const float* __restrict__ state,
               const float* __restrict__ Wu, const float* __restrict__ Wv,
               const float* __restrict__ Pp, float* __restrict__ out)
{
    const int t   = threadIdx.x;
    const int cta = blockIdx.x;

    // ================= one-time staging =================
    // W gate-paired: [k][gp][c], halves by gate parity
    for (int idx = t; idx < GPC*4*16; idx += NT) {
        int gl = idx >> 6, r = (idx >> 4) & 3, k4 = idx & 15;
        int gate = cta * GPC + gl;
        const float4* src = (const float4*)((gate < NG) ? Wu : Wv);
        int base = (gate < NG) ? gate : (gate - NG);
        float4 v = __ldg(src + (base + r*NG)*16 + k4);
        float vv[4] = {v.x, v.y, v.z, v.w};
        int gp = gl >> 1, ge = gl & 1;
        #pragma unroll
        for (int j = 0; j < 4; ++j) {
            int k = k4*4 + j;
            *(float*)(smem_raw + SM_W + k*2048 + gp*32 + r*8 + ge*4) = vv[j];
        }
    }
    // P_proj gate-paired: [gp][p]
    for (int idx = t; idx < NP*NGP; idx += NT) {
        int p = idx >> 6, gp = idx & 63;
        float2 v = __ldg((const float2*)(Pp + p*NGATE + cta*GPC + gp*2));
        *(float2*)(smem_raw + SM_P2 + gp*512 + p*8) = v;
    }
    // a scalar [k][b]
    for (int idx = t; idx < NB*NP; idx += NT) {
        int b = idx >> 6, k = idx & 63;
        *(float*)(smem_raw + SM_AS + k*128 + b*4) = state[idx];
    }
    // inv1 scalar [j][i]
    for (int m = t; m < NP*NP; m += NT)
        ((float*)(smem_raw + SM_INV))[m] = g_invT[0][m];

    // static mappings
    const int gp1 = t >> 4, bh = t & 15;               // phase 1: (gate-pair, b-half-pair)
    const char* wbase = smem_raw + SM_W + gp1*32;
    const char* abase = smem_raw + SM_AS + bh*8;
    const int b2 = t & 31, po = (t >> 5) & 15, gh = t >> 9;   // phase 2
    const int bp = t >> 6, iI = t & 63;                // update matvec

    float aprv[2] = {0, 0}, fprv[2] = {0, 0};

    __syncthreads();

    for (int it = 0; it < NITER; ++it) {
        // ========== phase 1: z = a@W^T (4 comps, gate-paired), f = u*dx + v*dy ==========
        u64 ac00=0, ac01=0, ac10=0, ac11=0, ac20=0, ac21=0, ac30=0, ac31=0;
        #pragma unroll 2
        for (int k = 0; k < NP; ++k) {
            ulonglong2 wA = *(const ulonglong2*)(wbase + k*2048);       // c0, c1
            ulonglong2 wB = *(const ulonglong2*)(wbase + k*2048 + 16);  // c2, c3
            float2 av = *(const float2*)(abase + k*128);
            u64 a0 = dup2(av.x), a1 = dup2(av.y);
            ac00 = fma2(wA.x, a0, ac00);  ac01 = fma2(wA.x, a1, ac01);
            ac10 = fma2(wA.y, a0, ac10);  ac11 = fma2(wA.y, a1, ac11);
            ac20 = fma2(wB.x, a0, ac20);  ac21 = fma2(wB.x, a1, ac21);
            ac30 = fma2(wB.y, a0, ac30);  ac31 = fma2(wB.y, a1, ac31);
        }
        {
            u64 f0 = fma2(ac10, ac30, mul2(ac00, ac20));   // b = 2bh
            u64 f1 = fma2(ac11, ac31, mul2(ac01, ac21));   // b = 2bh+1
            *(ulonglong2*)(smem_raw + SM_F2 + gp1*256 + bh*16) = make_ulonglong2(f0, f1);
        }
        __syncthreads();

        // ========== phase 2: S[b][p] += sum_gp f2[gp][b] .* P2[gp][p] ==========
        {
            u64 q0 = 0, q1 = 0, q2 = 0, q3 = 0;
            const char* pb = smem_raw + SM_P2 + po*32;
            const char* fb = smem_raw + SM_F2 + b2*8;
            const int g0 = gh*32, g1 = g0 + 32;
            #pragma unroll 4
            for (int gp = g0; gp < g1; ++gp) {
                ulonglong2 pA = *(const ulonglong2*)(pb + gp*512);
                ulonglong2 pB = *(const ulonglong2*)(pb + gp*512 + 16);
                u64 fv = *(const u64*)(fb + gp*256);
                q0 = fma2(fv, pA.x, q0);
                q1 = fma2(fv, pA.y, q1);
                q2 = fma2(fv, pB.x, q2);
                q3 = fma2(fv, pB.y, q3);
            }
            char* part = smem_raw + SM_PART + b2*512 + po*32;
            if (gh == 1) {
                *(ulonglong2*)(part)      = make_ulonglong2(q0, q1);
                *(ulonglong2*)(part + 16) = make_ulonglong2(q2, q3);
            }
            __syncthreads();
            if (gh == 0) {
                ulonglong2 rA = *(const ulonglong2*)(part);
                ulonglong2 rB = *(const ulonglong2*)(part + 16);
                q0 = add2(q0, rA.x); q1 = add2(q1, rA.y);
                q2 = add2(q2, rB.x); q3 = add2(q3, rB.y);
                float* Sb = g_S[it & 3] + b2*NP + po*4;
                float lo, hi;
                unpack2(q0, lo, hi); redadd(Sb    , lo + hi);
                unpack2(q1, lo, hi); redadd(Sb + 1, lo + hi);
                unpack2(q2, lo, hi); redadd(Sb + 2, lo + hi);
                unpack2(q3, lo, hi); redadd(Sb + 3, lo + hi);
            }
        }

        // ========== single global barrier ==========
        __threadfence();
        __syncthreads();
        if (t == 0) atom_inc_acqrel(&g_counter);
        if (it == NITER - 1 && cta != 0) return;      // non-CTA0 done; CTA0 finishes
        if (t == 0) {
            const unsigned tgt = (unsigned)NCTA * (unsigned)(it + 1);
            while (ldacq(&g_counter) < tgt) { }
        }
        __syncthreads();

        // zero the buffer used 1 iteration ago (reused at it+3; safe via barrier chain)
        if (t < 17) {
            int z = cta*17 + t;
            if (z < NB*NP) __stcg(&g_S[(it + 3) & 3][z], 0.0f);
        }

        // ========== update (redundant per CTA, in SMEM/regs) ==========
        {
            const float* Sb = g_S[it & 3];
            #pragma unroll
            for (int e = 0; e < 2; ++e) {
                int idx = t + e*NT;
                int b = idx >> 6, j = idx & 63;
                float f  = -__ldcv(Sb + idx);
                float av = *(const float*)(smem_raw + SM_AS + j*128 + b*4);
                float r;
                if (it == 0) r = av + DTF * f;
                else         r = 4.0f*av - aprv[e] + 4.0f*DTF*f - 2.0f*DTF*fprv[e];
                aprv[e] = av; fprv[e] = f;
                *(float*)(smem_raw + SM_R + j*128 + (b >> 1)*8 + (b & 1)*4) = r;
            }
        }
        __syncthreads();
        {
            // a_next = inv @ r : thread = (bp, i)
            u64 m = 0;
            const char* invb = smem_raw + SM_INV + iI*4;
            const char* rb   = smem_raw + SM_R + bp*8;
            #pragma unroll 4
            for (int j = 0; j < NP; ++j) {
                u64 rv = *(const u64*)(rb + j*128);
                u64 iv = dup2(*(const float*)(invb + j*256));
                m = fma2(rv, iv, m);
            }
            float lo, hi; unpack2(m, lo, hi);
            if (it < NITER - 1) {
                *(float*)(smem_raw + SM_AS + iI*128 + bp*8)     = lo;
                *(float*)(smem_raw + SM_AS + iI*128 + bp*8 + 4) = hi;
            } else { // only CTA0 reaches here
                out[(2*bp    )*NP + iI] = (lo - __ldg(&state[(2*bp    )*NP + iI])) * INV_DT_SKIP;
                out[(2*bp + 1)*NP + iI] = (hi - __ldg(&state[(2*bp + 1)*NP + iI])) * INV_DT_SKIP;
            }
        }
        if (it == 0) {  // switch to inv2 for remaining iterations
            __syncthreads();
            for (int m2 = t; m2 < NP*NP; m2 += NT)
                ((float*)(smem_raw + SM_INV))[m2] = g_invT[1][m2];
        }
        __syncthreads();
    }
}

// ---------------- launcher ----------------
extern "C" void kernel_launch(void* const* d_in, const int* in_sizes, int n_in,
                              void* d_out, int out_size) {
    const float* state = (const float*)d_in[0];
    const float* Ap    = (const float*)d_in[1];
    const float* Wu    = (const float*)d_in[2];
    const float* Wv    = (const float*)d_in[3];
    const float* Pp    = (const float*)d_in[4];
    float* out = (float*)d_out;
    (void)in_sizes; (void)n_in; (void)out_size;

    cudaFuncSetAttribute(persist_kernel,
                         cudaFuncAttributeMaxDynamicSharedMemorySize, SMEM_TOTAL);

    init_kernel<<<1, 256>>>(Ap);
    persist_kernel<<<NCTA, NT, SMEM_TOTAL>>>(state, Wu, Wv, Pp, out);
}

// round 7
// speedup vs baseline: 1.4428x; 1.4428x over previous
#include <cuda_runtime.h>

#define NG      8000
#define NGATE   16000
#define NCTA    125
#define GPC     128
#define NB      32
#define NP      64
#define NITER   50
#define NT      256
#define DTF     0.02f
#define INV_DT_SKIP 2.5f

typedef unsigned long long u64;

// ---------------- device scratch ----------------
__device__ float    g_S[4][NB*NP];        // rotating reduction buffers
__device__ float    g_invT[2][NP*NP];     // inverses, j-major: [j*64+i] = inv[i][j]
__device__ unsigned g_counter;

// ---------------- helpers ----------------
__device__ __forceinline__ u64 fma2(u64 a, u64 b, u64 c) {
    u64 d; asm("fma.rn.f32x2 %0, %1, %2, %3;" : "=l"(d) : "l"(a), "l"(b), "l"(c)); return d;
}
__device__ __forceinline__ u64 mul2(u64 a, u64 b) {
    u64 d; asm("mul.rn.f32x2 %0, %1, %2;" : "=l"(d) : "l"(a), "l"(b)); return d;
}
__device__ __forceinline__ u64 add2(u64 a, u64 b) {
    u64 d; asm("add.rn.f32x2 %0, %1, %2;" : "=l"(d) : "l"(a), "l"(b)); return d;
}
__device__ __forceinline__ u64 dup2(float x) {
    unsigned xi = __float_as_uint(x);
    u64 d; asm("mov.b64 %0, {%1, %2};" : "=l"(d) : "r"(xi), "r"(xi)); return d;
}
__device__ __forceinline__ void unpack2(u64 v, float& lo, float& hi) {
    unsigned a, b; asm("mov.b64 {%0, %1}, %2;" : "=r"(a), "=r"(b) : "l"(v));
    lo = __uint_as_float(a); hi = __uint_as_float(b);
}
__device__ __forceinline__ unsigned ldacq(const unsigned* p) {
    unsigned v; asm volatile("ld.acquire.gpu.u32 %0, [%1];" : "=r"(v) : "l"(p)); return v;
}
__device__ __forceinline__ unsigned atom_inc_acqrel(unsigned* p) {
    unsigned v, one = 1u;
    asm volatile("atom.add.acq_rel.gpu.u32 %0, [%1], %2;" : "=r"(v) : "l"(p), "r"(one)); return v;
}
__device__ __forceinline__ void redadd(float* p, float v) {
    asm volatile("red.add.f32 [%0], %1;" :: "l"(p), "f"(v));
}

// ---------------- init: matrix inverses + reset ----------------
__global__ void init_kernel(const float* __restrict__ Ap) {
    __shared__ float M[NP][2*NP + 1];
    __shared__ float fac[NP];
    __shared__ float s_piv;
    int t = threadIdx.x;

    for (int pass = 0; pass < 2; ++pass) {
        float dscale = (pass == 0) ? 1.0f : 3.0f;
        float ascale = (pass == 0) ? DTF : 2.0f * DTF;
        for (int idx = t; idx < NP*NP; idx += 256) {
            int i = idx >> 6, j = idx & 63;
            M[i][j]      = ((i == j) ? dscale : 0.0f) - ascale * Ap[idx];
            M[i][j + NP] = (i == j) ? 1.0f : 0.0f;
        }
        __syncthreads();
        for (int c = 0; c < NP; ++c) {
            if (t == 0) s_piv = 1.0f / M[c][c];
            __syncthreads();
            float ip = s_piv;
            if (t < 2*NP) M[c][t] *= ip;
            if (t < NP)   fac[t] = (t == c) ? 0.0f : M[t][c];
            __syncthreads();
            for (int idx = t; idx < NP * 2 * NP; idx += 256) {
                int r = idx >> 7, j = idx & 127;
                if (r != c) M[r][j] -= fac[r] * M[c][j];
            }
            __syncthreads();
        }
        for (int idx = t; idx < NP*NP; idx += 256) {
            int j = idx >> 6, i = idx & 63;
            g_invT[pass][idx] = M[i][j + NP];   // j-major
        }
        __syncthreads();
    }
    for (int idx = t; idx < 4*NB*NP; idx += 256) ((float*)g_S)[idx] = 0.0f;
    if (t == 0) g_counter = 0u;
    __threadfence();
}

// ---------------- SMEM layout (bytes) ----------------
#define SM_W     0                 // [gl 128][kslot 64][c 4] f32, k XOR (gl>>1)&7 : 131072
#define SM_P     131072            // [g 128][p 64] f32                            : 32768
#define SM_F     163840            // [g 128][bp 16] u64                           : 16384
#define SM_R     180224            // [j 64] stride 136B, 16 u64 b-pairs           : 8704
#define SM_PART  SM_F              // overlay on F+R: 192 slots x 128B             : 24576
#define SM_A     188928            // [k 64][bp 16] u64                            : 8192
#define SM_INV   197120            // [j 64][i 64] f32                             : 16384
#define SMEM_TOTAL 213504

extern __shared__ char smem_raw[];

__global__ void __launch_bounds__(NT, 1)
persist_kernel(const float* __restrict__ state,
               const float* __restrict__ Wu, const float* __restrict__ Wv,
               const float* __restrict__ Pp, float* __restrict__ out)
{
    const int t   = threadIdx.x;
    const int cta = blockIdx.x;

    // ================= one-time staging =================
    // W: [gl][kslot][c], kslot = k ^ ((gl>>1)&7)
    for (int idx = t; idx < GPC*4*16; idx += NT) {
        int gl = idx >> 6, r = (idx >> 4) & 3, k4 = idx & 15;
        int gate = cta * GPC + gl;
        const float4* src = (const float4*)((gate < NG) ? Wu : Wv);
        int base = (gate < NG) ? gate : (gate - NG);
        float4 v = __ldg(src + (base + r*NG)*16 + k4);
        float vv[4] = {v.x, v.y, v.z, v.w};
        int xr = (gl >> 1) & 7;
        #pragma unroll
        for (int j = 0; j < 4; ++j) {
            int k = k4*4 + j;
            *(float*)(smem_raw + SM_W + gl*1024 + (k ^ xr)*16 + r*4) = vv[j];
        }
    }
    // P: [g][p]
    for (int idx = t; idx < (GPC*NP)/4; idx += NT) {
        int p = idx >> 5, g4 = idx & 31;
        float4 v = __ldg((const float4*)(Pp + p*NGATE + cta*GPC + g4*4));
        float vv[4] = {v.x, v.y, v.z, v.w};
        #pragma unroll
        for (int j = 0; j < 4; ++j)
            *(float*)(smem_raw + SM_P + (g4*4 + j)*256 + p*4) = vv[j];
    }
    // a: [k][bp] u64
    for (int idx = t; idx < NB*NP; idx += NT) {
        int b = idx >> 6, k = idx & 63;
        *(float*)(smem_raw + SM_A + k*128 + (b >> 1)*8 + (b & 1)*4) = state[idx];
    }
    // inv1: [j][i]
    for (int m = t; m < NP*NP; m += NT)
        ((float*)(smem_raw + SM_INV))[m] = g_invT[0][m];

    // ---- static mappings ----
    // phase 1: thread = (gate-pair gp, batch-quarter bq)  -> gates 2gp,2gp+1; bp = bq*4..+3
    const int gp = t >> 2, bq = t & 3;
    const char* wb0 = smem_raw + SM_W + (2*gp)*1024;
    const char* wb1 = wb0 + 1024;
    const unsigned xr16 = ((unsigned)(gp & 7)) * 16u;
    const char* ab = smem_raw + SM_A + bq*32;
    // phase 2: thread = (bq2, p-quad p4, gate-quarter gh)
    const int bq2 = t & 3, p4 = (t >> 2) & 15, gh = t >> 6;
    // matvec: thread = (b-pair bpu, i-quad i4)
    const int bpu = t & 15, i4 = t >> 4;

    float aprv[8], fprv[8];
    #pragma unroll
    for (int e = 0; e < 8; ++e) { aprv[e] = 0.0f; fprv[e] = 0.0f; }

    __syncthreads();

    for (int it = 0; it < NITER; ++it) {
        // ========== phase 1: z = a@W^T (2 gates x 4 comps x 4 bp) ==========
        {
            u64 acc[2][4][4];
            #pragma unroll
            for (int g = 0; g < 2; ++g)
                #pragma unroll
                for (int c = 0; c < 4; ++c)
                    #pragma unroll
                    for (int i = 0; i < 4; ++i) acc[g][c][i] = 0;

            float4 w0 = *(const float4*)(wb0 + (0u ^ xr16));
            float4 w1 = *(const float4*)(wb1 + (0u ^ xr16));
            ulonglong2 aA = *(const ulonglong2*)(ab);
            ulonglong2 aB = *(const ulonglong2*)(ab + 16);

            #pragma unroll 1
            for (int k = 0; k < NP; ++k) {
                float4 nw0, nw1; ulonglong2 nA, nB;
                if (k < NP - 1) {
                    unsigned off = ((unsigned)((k + 1) * 16)) ^ xr16;
                    nw0 = *(const float4*)(wb0 + off);
                    nw1 = *(const float4*)(wb1 + off);
                    nA  = *(const ulonglong2*)(ab + (k + 1)*128);
                    nB  = *(const ulonglong2*)(ab + (k + 1)*128 + 16);
                }
                u64 av[4] = {aA.x, aA.y, aB.x, aB.y};
                u64 d0[4] = {dup2(w0.x), dup2(w0.y), dup2(w0.z), dup2(w0.w)};
                u64 d1[4] = {dup2(w1.x), dup2(w1.y), dup2(w1.z), dup2(w1.w)};
                #pragma unroll
                for (int c = 0; c < 4; ++c)
                    #pragma unroll
                    for (int i = 0; i < 4; ++i) {
                        acc[0][c][i] = fma2(d0[c], av[i], acc[0][c][i]);
                        acc[1][c][i] = fma2(d1[c], av[i], acc[1][c][i]);
                    }
                if (k < NP - 1) { w0 = nw0; w1 = nw1; aA = nA; aB = nB; }
            }
            // f = u*dx + v*dy, store [g][bp]
            #pragma unroll
            for (int g = 0; g < 2; ++g) {
                u64 f0 = fma2(acc[g][1][0], acc[g][3][0], mul2(acc[g][0][0], acc[g][2][0]));
                u64 f1 = fma2(acc[g][1][1], acc[g][3][1], mul2(acc[g][0][1], acc[g][2][1]));
                u64 f2 = fma2(acc[g][1][2], acc[g][3][2], mul2(acc[g][0][2], acc[g][2][2]));
                u64 f3 = fma2(acc[g][1][3], acc[g][3][3], mul2(acc[g][0][3], acc[g][2][3]));
                char* fb = smem_raw + SM_F + (2*gp + g)*128 + bq*32;
                *(ulonglong2*)(fb)      = make_ulonglong2(f0, f1);
                *(ulonglong2*)(fb + 16) = make_ulonglong2(f2, f3);
            }
        }
        __syncthreads();

        // ========== phase 2: q[p][bp] = sum_{g in quarter} f[g][bp]*P[g][p] ==========
        u64 q[4][4];
        #pragma unroll
        for (int p = 0; p < 4; ++p)
            #pragma unroll
            for (int i = 0; i < 4; ++i) q[p][i] = 0;
        {
            const char* fb = smem_raw + SM_F + bq2*32;
            const char* pb = smem_raw + SM_P + p4*16;
            const int g0 = gh*32, g1 = g0 + 32;
            #pragma unroll 2
            for (int g = g0; g < g1; ++g) {
                ulonglong2 fA = *(const ulonglong2*)(fb + g*128);
                ulonglong2 fB = *(const ulonglong2*)(fb + g*128 + 16);
                float4 pv = *(const float4*)(pb + g*256);
                u64 fv[4] = {fA.x, fA.y, fB.x, fB.y};
                u64 pd[4] = {dup2(pv.x), dup2(pv.y), dup2(pv.z), dup2(pv.w)};
                #pragma unroll
                for (int p = 0; p < 4; ++p)
                    #pragma unroll
                    for (int i = 0; i < 4; ++i)
                        q[p][i] = fma2(pd[p], fv[i], q[p][i]);
            }
        }
        __syncthreads();   // f reads complete; PART may overlay F/R
        if (gh != 0) {
            int slot = (gh - 1)*64 + (t & 63);
            char* pa = smem_raw + SM_PART + slot*128;
            unsigned sx = (unsigned)(slot & 7) * 16u;
            #pragma unroll
            for (int jp = 0; jp < 8; ++jp) {
                int j0 = jp*2;
                *(ulonglong2*)(pa + (((unsigned)(jp*16)) ^ sx)) =
                    make_ulonglong2(q[j0 >> 2][j0 & 3], q[(j0+1) >> 2][(j0+1) & 3]);
            }
        }
        __syncthreads();
        if (gh == 0) {
            #pragma unroll
            for (int h = 0; h < 3; ++h) {
                int slot = h*64 + t;     // t < 64 here
                const char* pa = smem_raw + SM_PART + slot*128;
                unsigned sx = (unsigned)(slot & 7) * 16u;
                #pragma unroll
                for (int jp = 0; jp < 8; ++jp) {
                    ulonglong2 v = *(const ulonglong2*)(pa + (((unsigned)(jp*16)) ^ sx));
                    int j0 = jp*2;
                    q[j0 >> 2][j0 & 3]         = add2(q[j0 >> 2][j0 & 3], v.x);
                    q[(j0+1) >> 2][(j0+1) & 3] = add2(q[(j0+1) >> 2][(j0+1) & 3], v.y);
                }
            }
            float* Sb = g_S[it & 3];
            #pragma unroll
            for (int p = 0; p < 4; ++p)
                #pragma unroll
                for (int i = 0; i < 4; ++i) {
                    int b = 2*(bq2*4 + i), pp = p4*4 + p;
                    float lo, hi; unpack2(q[p][i], lo, hi);
                    redadd(Sb + b*NP + pp, lo);
                    redadd(Sb + (b + 1)*NP + pp, hi);
                }
        }

        // ========== single global barrier ==========
        __threadfence();
        __syncthreads();
        if (t == 0) atom_inc_acqrel(&g_counter);
        if (it == NITER - 1 && cta != 0) return;
        if (t == 0) {
            const unsigned tgt = (unsigned)NCTA * (unsigned)(it + 1);
            while (ldacq(&g_counter) < tgt) { }
        }
        __syncthreads();

        // zero buffer used 1 iter ago (next written at it+3; ordered by barrier chain)
        if (t < 17) {
            int z = cta*17 + t;
            if (z < NB*NP) __stcg(&g_S[(it + 3) & 3][z], 0.0f);
        }

        // ========== update step 1: r ==========
        {
            const float* Sb = g_S[it & 3];
            #pragma unroll
            for (int e = 0; e < 8; ++e) {
                int idx = t + e*NT;
                int b = idx >> 6, j = idx & 63;
                float f  = -__ldcv(Sb + idx);
                float av = *(const float*)(smem_raw + SM_A + j*128 + (b >> 1)*8 + (b & 1)*4);
                float r;
                if (it == 0) r = av + DTF * f;
                else         r = 4.0f*av - aprv[e] + 4.0f*DTF*f - 2.0f*DTF*fprv[e];
                aprv[e] = av; fprv[e] = f;
                *(float*)(smem_raw + SM_R + j*136 + (b >> 1)*8 + (b & 1)*4) = r;
            }
        }
        __syncthreads();

        // ========== update step 2: a_next = inv @ r ==========
        {
            u64 m[4] = {0, 0, 0, 0};
            const char* invb = smem_raw + SM_INV + i4*16;
            const char* rb   = smem_raw + SM_R + bpu*8;
            #pragma unroll 4
            for (int j = 0; j < NP; ++j) {
                u64 rv = *(const u64*)(rb + j*136);
                float4 iv = *(const float4*)(invb + j*256);
                m[0] = fma2(rv, dup2(iv.x), m[0]);
                m[1] = fma2(rv, dup2(iv.y), m[1]);
                m[2] = fma2(rv, dup2(iv.z), m[2]);
                m[3] = fma2(rv, dup2(iv.w), m[3]);
            }
            if (it < NITER - 1) {
                #pragma unroll
                for (int qq = 0; qq < 4; ++qq)
                    *(u64*)(smem_raw + SM_A + (i4*4 + qq)*128 + bpu*8) = m[qq];
            } else {   // only CTA0 reaches here
                #pragma unroll
                for (int qq = 0; qq < 4; ++qq) {
                    int i = i4*4 + qq;
                    float lo, hi; unpack2(m[qq], lo, hi);
                    out[(2*bpu    )*NP + i] = (lo - __ldg(&state[(2*bpu    )*NP + i])) * INV_DT_SKIP;
                    out[(2*bpu + 1)*NP + i] = (hi - __ldg(&state[(2*bpu + 1)*NP + i])) * INV_DT_SKIP;
                }
            }
        }
        if (it == 0) {   // switch to inv2
            __syncthreads();
            for (int m2 = t; m2 < NP*NP; m2 += NT)
                ((float*)(smem_raw + SM_INV))[m2] = g_invT[1][m2];
        }
        __syncthreads();
    }
}

// ---------------- launcher ----------------
extern "C" void kernel_launch(void* const* d_in, const int* in_sizes, int n_in,
                              void* d_out, int out_size) {
    const float* state = (const float*)d_in[0];
    const float* Ap    = (const float*)d_in[1];
    const float* Wu    = (const float*)d_in[2];
    const float* Wv    = (const float*)d_in[3];
    const float* Pp    = (const float*)d_in[4];
    float* out = (float*)d_out;
    (void)in_sizes; (void)n_in; (void)out_size;

    cudaFuncSetAttribute(persist_kernel,
                         cudaFuncAttributeMaxDynamicSharedMemorySize, SMEM_TOTAL);

    init_kernel<<<1, 256>>>(Ap);
    persist_kernel<<<NCTA, NT, SMEM_TOTAL>>>(state, Wu, Wv, Pp, out);
}

// round 9
// speedup vs baseline: 1.4917x; 1.0339x over previous
#include <cuda_runtime.h>

#define NG      8000
#define NGATE   16000
#define NCTA    250
#define GPC     64
#define NB      32
#define NP      64
#define NITER   50
#define NT      256
#define DTF     0.02f
#define INV_DT_SKIP 2.5f

typedef unsigned long long u64;

// ---------------- device scratch ----------------
__device__ float    g_S[4][NB*NP];        // rotating reduction buffers
__device__ float    g_invT[2][NP*NP];     // inverses, j-major: [j*64+i] = inv[i][j]
__device__ unsigned g_counter;

// ---------------- helpers ----------------
__device__ __forceinline__ u64 fma2(u64 a, u64 b, u64 c) {
    u64 d; asm("fma.rn.f32x2 %0, %1, %2, %3;" : "=l"(d) : "l"(a), "l"(b), "l"(c)); return d;
}
__device__ __forceinline__ u64 mul2(u64 a, u64 b) {
    u64 d; asm("mul.rn.f32x2 %0, %1, %2;" : "=l"(d) : "l"(a), "l"(b)); return d;
}
__device__ __forceinline__ u64 add2(u64 a, u64 b) {
    u64 d; asm("add.rn.f32x2 %0, %1, %2;" : "=l"(d) : "l"(a), "l"(b)); return d;
}
__device__ __forceinline__ u64 dup2(float x) {
    unsigned xi = __float_as_uint(x);
    u64 d; asm("mov.b64 %0, {%1, %2};" : "=l"(d) : "r"(xi), "r"(xi)); return d;
}
__device__ __forceinline__ void unpack2(u64 v, float& lo, float& hi) {
    unsigned a, b; asm("mov.b64 {%0, %1}, %2;" : "=r"(a), "=r"(b) : "l"(v));
    lo = __uint_as_float(a); hi = __uint_as_float(b);
}
__device__ __forceinline__ unsigned ldacq(const unsigned* p) {
    unsigned v; asm volatile("ld.acquire.gpu.u32 %0, [%1];" : "=r"(v) : "l"(p)); return v;
}
__device__ __forceinline__ unsigned atom_inc_acqrel(unsigned* p) {
    unsigned v, one = 1u;
    asm volatile("atom.add.acq_rel.gpu.u32 %0, [%1], %2;" : "=r"(v) : "l"(p), "r"(one)); return v;
}
__device__ __forceinline__ void redadd(float* p, float v) {
    asm volatile("red.add.f32 [%0], %1;" :: "l"(p), "f"(v));
}

// ---------------- init: matrix inverses + reset ----------------
__global__ void init_kernel(const float* __restrict__ Ap) {
    __shared__ float M[NP][2*NP + 1];
    __shared__ float fac[NP];
    __shared__ float s_piv;
    int t = threadIdx.x;

    for (int pass = 0; pass < 2; ++pass) {
        float dscale = (pass == 0) ? 1.0f : 3.0f;
        float ascale = (pass == 0) ? DTF : 2.0f * DTF;
        for (int idx = t; idx < NP*NP; idx += 256) {
            int i = idx >> 6, j = idx & 63;
            M[i][j]      = ((i == j) ? dscale : 0.0f) - ascale * Ap[idx];
            M[i][j + NP] = (i == j) ? 1.0f : 0.0f;
        }
        __syncthreads();
        for (int c = 0; c < NP; ++c) {
            if (t == 0) s_piv = 1.0f / M[c][c];
            __syncthreads();
            float ip = s_piv;
            if (t < 2*NP) M[c][t] *= ip;
            if (t < NP)   fac[t] = (t == c) ? 0.0f : M[t][c];
            __syncthreads();
            for (int idx = t; idx < NP * 2 * NP; idx += 256) {
                int r = idx >> 7, j = idx & 127;
                if (r != c) M[r][j] -= fac[r] * M[c][j];
            }
            __syncthreads();
        }
        for (int idx = t; idx < NP*NP; idx += 256) {
            int j = idx >> 6, i = idx & 63;
            g_invT[pass][idx] = M[i][j + NP];   // j-major
        }
        __syncthreads();
    }
    for (int idx = t; idx < 4*NB*NP; idx += 256) ((float*)g_S)[idx] = 0.0f;
    if (t == 0) g_counter = 0u;
    __threadfence();
}

// ---------------- SMEM layout (bytes) ----------------
#define SM_W     0                 // [g 64][kslot 64][c 4] f32, k XOR (g&7)  : 65536
#define SM_P     65536             // [g 64][p 64] f32                        : 16384
#define SM_F     81920             // [g 64] stride 144B (16 u64 b-pairs)     : 9216
#define SM_A     91136             // [k 64][bp 16] u64                       : 8192
#define SM_R     99328             // [j 64] stride 136B                      : 8704
#define SM_PART  SM_F              // overlay on F: 128 slots x 64B = 8192
#define SMEM_TOTAL 108032

extern __shared__ char smem_raw[];

__global__ void __launch_bounds__(NT, 2)
persist_kernel(const float* __restrict__ state,
               const float* __restrict__ Wu, const float* __restrict__ Wv,
               const float* __restrict__ Pp, float* __restrict__ out)
{
    const int t   = threadIdx.x;
    const int cta = blockIdx.x;

    // ================= one-time staging =================
    // W: [g][kslot][c], kslot = k ^ (g&7)
    for (int idx = t; idx < GPC*4*16; idx += NT) {
        int g = idx >> 6, r = (idx >> 4) & 3, k4 = idx & 15;
        int gate = cta * GPC + g;
        const float4* src = (const float4*)((gate < NG) ? Wu : Wv);
        int base = (gate < NG) ? gate : (gate - NG);
        float4 v = __ldg(src + (base + r*NG)*16 + k4);
        float vv[4] = {v.x, v.y, v.z, v.w};
        int xr = g & 7;
        #pragma unroll
        for (int j = 0; j < 4; ++j) {
            int k = k4*4 + j;
            *(float*)(smem_raw + SM_W + g*1024 + (k ^ xr)*16 + r*4) = vv[j];
        }
    }
    // P: [g][p]
    for (int idx = t; idx < (GPC*NP)/4; idx += NT) {
        int p = idx >> 4, g4 = idx & 15;
        float4 v = __ldg((const float4*)(Pp + p*NGATE + cta*GPC + g4*4));
        float vv[4] = {v.x, v.y, v.z, v.w};
        #pragma unroll
        for (int j = 0; j < 4; ++j)
            *(float*)(smem_raw + SM_P + (g4*4 + j)*256 + p*4) = vv[j];
    }
    // a: [k][bp] u64
    for (int idx = t; idx < NB*NP; idx += NT) {
        int b = idx >> 6, k = idx & 63;
        *(float*)(smem_raw + SM_A + k*128 + (b >> 1)*8 + (b & 1)*4) = state[idx];
    }

    // ---- static mappings ----
    // phase 1: thread = (gate g1, batch-quarter bq)
    const int g1 = t >> 2, bq = t & 3;
    const char* wb = smem_raw + SM_W + g1*1024;
    const unsigned xr16 = ((unsigned)(g1 & 7)) * 16u;
    const char* ab = smem_raw + SM_A + bq*32;
    // phase 2: thread = (bq2 4, p8 32, gh 2)
    const int bq2 = t & 3, p8 = (t >> 2) & 31, gh = t >> 7;
    // matvec: thread = (b-pair bpu 16, i-quad i4 16)
    const int bpu = t & 15, i4 = t >> 4;

    float aprv[8], fprv[8];
    #pragma unroll
    for (int e = 0; e < 8; ++e) { aprv[e] = 0.0f; fprv[e] = 0.0f; }

    __syncthreads();

    for (int it = 0; it < NITER; ++it) {
        // ========== phase 1: z = a@W^T (1 gate x 4 comps x 4 bp) ==========
        {
            u64 acc[4][4];
            #pragma unroll
            for (int c = 0; c < 4; ++c)
                #pragma unroll
                for (int i = 0; i < 4; ++i) acc[c][i] = 0;

            #pragma unroll 4
            for (int k = 0; k < NP; ++k) {
                float4 w = *(const float4*)(wb + (((unsigned)(k * 16)) ^ xr16));
                ulonglong2 aA = *(const ulonglong2*)(ab + k*128);
                ulonglong2 aB = *(const ulonglong2*)(ab + k*128 + 16);
                u64 av[4] = {aA.x, aA.y, aB.x, aB.y};
                u64 d[4] = {dup2(w.x), dup2(w.y), dup2(w.z), dup2(w.w)};
                #pragma unroll
                for (int c = 0; c < 4; ++c)
                    #pragma unroll
                    for (int i = 0; i < 4; ++i)
                        acc[c][i] = fma2(d[c], av[i], acc[c][i]);
            }
            // f = u*dx + v*dy
            u64 f0 = fma2(acc[1][0], acc[3][0], mul2(acc[0][0], acc[2][0]));
            u64 f1 = fma2(acc[1][1], acc[3][1], mul2(acc[0][1], acc[2][1]));
            u64 f2 = fma2(acc[1][2], acc[3][2], mul2(acc[0][2], acc[2][2]));
            u64 f3 = fma2(acc[1][3], acc[3][3], mul2(acc[0][3], acc[2][3]));
            char* fb = smem_raw + SM_F + g1*144 + bq*32;
            *(ulonglong2*)(fb)      = make_ulonglong2(f0, f1);
            *(ulonglong2*)(fb + 16) = make_ulonglong2(f2, f3);
        }
        __syncthreads();

        // ========== phase 2: q[2p][4bp] over half the gates ==========
        u64 q[2][4];
        #pragma unroll
        for (int p = 0; p < 2; ++p)
            #pragma unroll
            for (int i = 0; i < 4; ++i) q[p][i] = 0;
        {
            const char* fb = smem_raw + SM_F + bq2*32;
            const char* pb = smem_raw + SM_P + p8*8;
            const int gg0 = gh*32, gg1 = gg0 + 32;
            #pragma unroll 4
            for (int g = gg0; g < gg1; ++g) {
                ulonglong2 fA = *(const ulonglong2*)(fb + g*144);
                ulonglong2 fB = *(const ulonglong2*)(fb + g*144 + 16);
                float2 pv = *(const float2*)(pb + g*256);
                u64 fv[4] = {fA.x, fA.y, fB.x, fB.y};
                u64 pd0 = dup2(pv.x), pd1 = dup2(pv.y);
                #pragma unroll
                for (int i = 0; i < 4; ++i) {
                    q[0][i] = fma2(pd0, fv[i], q[0][i]);
                    q[1][i] = fma2(pd1, fv[i], q[1][i]);
                }
            }
        }
        __syncthreads();   // f fully consumed; PART may overlay F
        {
            int slot = bq2*32 + p8;
            char* pa = smem_raw + SM_PART + slot*64;
            if (gh == 1) {
                *(ulonglong2*)(pa)      = make_ulonglong2(q[0][0], q[0][1]);
                *(ulonglong2*)(pa + 16) = make_ulonglong2(q[0][2], q[0][3]);
                *(ulonglong2*)(pa + 32) = make_ulonglong2(q[1][0], q[1][1]);
                *(ulonglong2*)(pa + 48) = make_ulonglong2(q[1][2], q[1][3]);
            }
            __syncthreads();
            if (gh == 0) {
                ulonglong2 v0 = *(const ulonglong2*)(pa);
                ulonglong2 v1 = *(const ulonglong2*)(pa + 16);
                ulonglong2 v2 = *(const ulonglong2*)(pa + 32);
                ulonglong2 v3 = *(const ulonglong2*)(pa + 48);
                q[0][0] = add2(q[0][0], v0.x); q[0][1] = add2(q[0][1], v0.y);
                q[0][2] = add2(q[0][2], v1.x); q[0][3] = add2(q[0][3], v1.y);
                q[1][0] = add2(q[1][0], v2.x); q[1][1] = add2(q[1][1], v2.y);
                q[1][2] = add2(q[1][2], v3.x); q[1][3] = add2(q[1][3], v3.y);
                float* Sb = g_S[it & 3];
                #pragma unroll
                for (int p = 0; p < 2; ++p)
                    #pragma unroll
                    for (int i = 0; i < 4; ++i) {
                        int b = 2*(bq2*4 + i), pp = p8*2 + p;
                        float lo, hi; unpack2(q[p][i], lo, hi);
                        redadd(Sb + b*NP + pp, lo);
                        redadd(Sb + (b + 1)*NP + pp, hi);
                    }
            }
        }

        // ========== single global barrier ==========
        __threadfence();
        __syncthreads();
        if (t == 0) atom_inc_acqrel(&g_counter);
        if (it == NITER - 1 && cta != 0) return;
        if (t == 0) {
            const unsigned tgt = (unsigned)NCTA * (unsigned)(it + 1);
            while (ldacq(&g_counter) < tgt) { }
        }
        __syncthreads();

        // zero buffer used 1 iter ago (rewritten at it+3; ordered by barrier chain)
        if (t < 9) {
            int z = cta*9 + t;
            if (z < NB*NP) __stcg(&g_S[(it + 3) & 3][z], 0.0f);
        }

        // ========== update step 1: r ==========
        {
            const float* Sb = g_S[it & 3];
            #pragma unroll
            for (int e = 0; e < 8; ++e) {
                int idx = t + e*NT;
                int b = idx >> 6, j = idx & 63;
                float f  = -__ldcv(Sb + idx);
                float av = *(const float*)(smem_raw + SM_A + j*128 + (b >> 1)*8 + (b & 1)*4);
                float r;
                if (it == 0) r = av + DTF * f;
                else         r = 4.0f*av - aprv[e] + 4.0f*DTF*f - 2.0f*DTF*fprv[e];
                aprv[e] = av; fprv[e] = f;
                *(float*)(smem_raw + SM_R + j*136 + (b >> 1)*8 + (b & 1)*4) = r;
            }
        }
        __syncthreads();

        // ========== update step 2: a_next = inv @ r (inv from L1/L2) ==========
        {
            const float* invg = g_invT[(it == 0) ? 0 : 1];
            u64 m[4] = {0, 0, 0, 0};
            const char* rb = smem_raw + SM_R + bpu*8;
            #pragma unroll 4
            for (int j = 0; j < NP; ++j) {
                u64 rv = *(const u64*)(rb + j*136);
                float4 iv = __ldg((const float4*)(invg + j*64 + i4*4));
                m[0] = fma2(rv, dup2(iv.x), m[0]);
                m[1] = fma2(rv, dup2(iv.y), m[1]);
                m[2] = fma2(rv, dup2(iv.z), m[2]);
                m[3] = fma2(rv, dup2(iv.w), m[3]);
            }
            if (it < NITER - 1) {
                #pragma unroll
                for (int qq = 0; qq < 4; ++qq)
                    *(u64*)(smem_raw + SM_A + (i4*4 + qq)*128 + bpu*8) = m[qq];
            } else {   // only CTA0 reaches here
                #pragma unroll
                for (int qq = 0; qq < 4; ++qq) {
                    int i = i4*4 + qq;
                    float lo, hi; unpack2(m[qq], lo, hi);
                    out[(2*bpu    )*NP + i] = (lo - __ldg(&state[(2*bpu    )*NP + i])) * INV_DT_SKIP;
                    out[(2*bpu + 1)*NP + i] = (hi - __ldg(&state[(2*bpu + 1)*NP + i])) * INV_DT_SKIP;
                }
            }
        }
        __syncthreads();
    }
}

// ---------------- launcher ----------------
extern "C" void kernel_launch(void* const* d_in, const int* in_sizes, int n_in,
                              void* d_out, int out_size) {
    const float* state = (const float*)d_in[0];
    const float* Ap    = (const float*)d_in[1];
    const float* Wu    = (const float*)d_in[2];
    const float* Wv    = (const float*)d_in[3];
    const float* Pp    = (const float*)d_in[4];
    float* out = (float*)d_out;
    (void)in_sizes; (void)n_in; (void)out_size;

    cudaFuncSetAttribute(persist_kernel,
                         cudaFuncAttributeMaxDynamicSharedMemorySize, SMEM_TOTAL);

    init_kernel<<<1, 256>>>(Ap);
    persist_kernel<<<NCTA, NT, SMEM_TOTAL>>>(state, Wu, Wv, Pp, out);
}